// round 13
// baseline (speedup 1.0000x reference)
#include <cuda_runtime.h>

// R13: R12 (41.7us, best) + loop-phase warp remap for trip-count balance.
// Warp = 2 batches x 16 consecutive tokens -> paid pair-iters/batch drops
// 48 -> 40 (lane efficiency 69% -> 82.5%). Loop body, smem k/v layout, and
// coalesced store path are byte-identical to R12. Prologue additionally
// stages packed Q and digs so the loop phase can run a different (b,t) than
// the prologue token.

#define T 64
#define BPB 4
#define NTHREADS (BPB * T)
#define VOCAB 10

typedef unsigned long long u64;

__device__ __forceinline__ float ex2f(float x) {
    float y; asm("ex2.approx.ftz.f32 %0, %1;" : "=f"(y) : "f"(x)); return y;
}
__device__ __forceinline__ float rcpf(float x) {
    float y; asm("rcp.approx.ftz.f32 %0, %1;" : "=f"(y) : "f"(x)); return y;
}
__device__ __forceinline__ u64 pack2(float lo, float hi) {
    u64 r; asm("mov.b64 %0, {%1, %2};" : "=l"(r) : "f"(lo), "f"(hi)); return r;
}
__device__ __forceinline__ void unpack2(u64 v, float& lo, float& hi) {
    asm("mov.b64 {%0, %1}, %2;" : "=f"(lo), "=f"(hi) : "l"(v));
}
__device__ __forceinline__ u64 fma2(u64 a, u64 b, u64 c) {
    u64 d; asm("fma.rn.f32x2 %0, %1, %2, %3;" : "=l"(d) : "l"(a), "l"(b), "l"(c)); return d;
}
__device__ __forceinline__ u64 mul2(u64 a, u64 b) {
    u64 d; asm("mul.rn.f32x2 %0, %1, %2;" : "=l"(d) : "l"(a), "l"(b)); return d;
}
__device__ __forceinline__ u64 add2(u64 a, u64 b) {
    u64 d; asm("add.rn.f32x2 %0, %1, %2;" : "=l"(d) : "l"(a), "l"(b)); return d;
}

__global__ __launch_bounds__(NTHREADS)
void adder_model_kernel(
    const int* __restrict__ idx,
    const float* __restrict__ pA,
    const float* __restrict__ pStart,
    const float* __restrict__ pStride,
    const float* __restrict__ w_ln1,
    const float* __restrict__ w_ln2,
    const float* __restrict__ w_lnf,
    const float* __restrict__ w_qn,
    const float* __restrict__ Wq,
    const float* __restrict__ Wk,
    const float* __restrict__ Wg,
    const float* __restrict__ Wu,
    const float* __restrict__ Wd,
    float* __restrict__ out)
{
    // pair-interleaved: kA[b][i] = {pack(k0[2i],k0[2i+1]), pack(k1[2i],k1[2i+1])}
    __shared__ ulonglong2 kA[BPB][T / 2];
    __shared__ ulonglong2 kB[BPB][T / 2];
    __shared__ ulonglong2 vA[BPB][T / 2];   // (vq0 pair, vq1 pair)
    __shared__ u64        vC[BPB][T / 2];   // vq2 pair
    __shared__ u64        smQxy[BPB * T];   // packed scaled Q (q0,q1)
    __shared__ u64        smQzw[BPB * T];   // packed scaled Q (q2,q3)
    __shared__ int        digs_sh[BPB * T];
    __shared__ float2 table_sh[VOCAB];
    __shared__ float  logits_sh[BPB * T * VOCAB];

    const int tid = threadIdx.x;

    const float A       = pA[0];
    const float astart  = pStart[0];
    const float astride = pStride[0];

    // digit table (shared across block)
    if (tid < VOCAB) {
        float s, c;
        __sincosf(astart + (float)tid * astride, &s, &c);
        table_sh[tid] = make_float2(A * c, A * s);
    }

    // ================= prologue: token (bp, tp) by linear tid =================
    {
        const int bp = tid >> 6;             // batch within block
        const int tp = tid & 63;             // token

        const int dig = idx[(size_t)(blockIdx.x * BPB + bp) * T + tp];
        digs_sh[tid] = dig;
        float sa, ca;
        __sincosf(astart + (float)dig * astride, &sa, &ca);
        const float x0 = A * ca;
        const float x1 = A * sa;
        const float x2 = __sinf((float)tp * 1.0e-4f);

        // RMS ln1
        const float r = rsqrtf((x0*x0 + x1*x1 + x2*x2) * (1.0f/3.0f) + 1e-6f);
        const float h0 = x0 * r * w_ln1[0];
        const float h1 = x1 * r * w_ln1[1];
        const float h2 = x2 * r * w_ln1[2];

        float qr[4], kv[4];
#pragma unroll
        for (int j = 0; j < 4; ++j) {
            qr[j] = h0 * Wq[j*3+0] + h1 * Wq[j*3+1] + h2 * Wq[j*3+2];
            kv[j] = h0 * Wk[j*3+0] + h1 * Wk[j*3+1] + h2 * Wk[j*3+2];
        }

        // v pre-projected through Wq
        const float vq0 = kv[0]*Wq[0] + kv[1]*Wq[3] + kv[2]*Wq[6] + kv[3]*Wq[9];
        const float vq1 = kv[0]*Wq[1] + kv[1]*Wq[4] + kv[2]*Wq[7] + kv[3]*Wq[10];
        const float vq2 = kv[0]*Wq[2] + kv[1]*Wq[5] + kv[2]*Wq[8] + kv[3]*Wq[11];

        const float wq0 = w_qn[0], wq1 = w_qn[1], wq2 = w_qn[2], wq3 = w_qn[3];
        const float rq = rsqrtf((qr[0]*qr[0]+qr[1]*qr[1]+qr[2]*qr[2]+qr[3]*qr[3]) * 0.25f + 1e-6f);
        const float rk = rsqrtf((kv[0]*kv[0]+kv[1]*kv[1]+kv[2]*kv[2]+kv[3]*kv[3]) * 0.25f + 1e-6f);
        const float q0 = qr[0]*rq*wq0, q1 = qr[1]*rq*wq1;
        const float q2 = qr[2]*rq*wq2, q3 = qr[3]*rq*wq3;
        const float k0 = kv[0]*rk*wq0, k1 = kv[1]*rk*wq1;
        const float k2 = kv[2]*rk*wq2, k3 = kv[3]*rk*wq3;

        // RoPE (theta=3, HD=4)
        float s0, c0, s1, c1;
        __sincosf((float)tp, &s0, &c0);
        __sincosf((float)tp * 0.57735026918962576f, &s1, &c1);

        const float SC = 0.5f * 1.4426950408889634f;   // scale * log2(e)
        const float Q0 = (q0*c0 - q1*s0) * SC, Q1 = (q0*s0 + q1*c0) * SC;
        const float Q2 = (q2*c1 - q3*s1) * SC, Q3 = (q2*s1 + q3*c1) * SC;
        const float K0 = k0*c0 - k1*s0, K1 = k0*s0 + k1*c0;
        const float K2 = k2*c1 - k3*s1, K3 = k2*s1 + k3*c1;

        smQxy[tid] = pack2(Q0, Q1);
        smQzw[tid] = pack2(Q2, Q3);

        const int i = tp >> 1, lane = tp & 1;
        float* a = (float*)&kA[bp][i]; a[lane] = K0; a[2 + lane] = K1;
        float* bb = (float*)&kB[bp][i]; bb[lane] = K2; bb[2 + lane] = K3;
        float* c = (float*)&vA[bp][i]; c[lane] = vq0; c[2 + lane] = vq1;
        float* d = (float*)&vC[bp][i]; d[lane] = vq2;
    }
    __syncthreads();

    // ============ loop phase: warp = 2 batches x 16 consecutive tokens ============
    const int w    = tid >> 5;
    const int lane = tid & 31;
    const int qtr  = w & 3;                    // token quarter 0..3
    const int bl   = 2 * (w >> 2) + (lane >> 4);
    const int t    = 16 * qtr + (lane & 15);

    float Q0, Q1, Q2, Q3;
    unpack2(smQxy[bl * T + t], Q0, Q1);
    unpack2(smQzw[bl * T + t], Q2, Q3);
    const u64 Q0d = pack2(Q0, Q0), Q1d = pack2(Q1, Q1);
    const u64 Q2d = pack2(Q2, Q2), Q3d = pack2(Q3, Q3);

    u64 sum2 = 0ULL, c0a = 0ULL, c1a = 0ULL, c2a = 0ULL;
    const int np = (t + 1) >> 1;      // full pairs: s in [0, 2*np)
#pragma unroll 4
    for (int i = 0; i < np; ++i) {
        const ulonglong2 ka = kA[bl][i];
        const ulonglong2 kb = kB[bl][i];
        const u64 sc2 = fma2(Q0d, ka.x, fma2(Q1d, ka.y, fma2(Q2d, kb.x, mul2(Q3d, kb.y))));
        float sl, sh; unpack2(sc2, sl, sh);
        const u64 p2 = pack2(ex2f(sl), ex2f(sh));
        sum2 = add2(sum2, p2);
        const ulonglong2 va = vA[bl][i];
        const u64 vc = vC[bl][i];
        c0a = fma2(p2, va.x, c0a);
        c1a = fma2(p2, va.y, c1a);
        c2a = fma2(p2, vc,   c2a);
    }
    float sl, sh, a0, a1, a2, tl, th;
    unpack2(sum2, sl, sh); float sum = sl + sh;
    unpack2(c0a, tl, th); a0 = tl + th;
    unpack2(c1a, tl, th); a1 = tl + th;
    unpack2(c2a, tl, th); a2 = tl + th;

    if (!(t & 1)) {                   // leftover s = t (self term) from smem
        const int i = t >> 1;
        const float* ka = (const float*)&kA[bl][i];
        const float* kb = (const float*)&kB[bl][i];
        const float* va = (const float*)&vA[bl][i];
        const float* vc = (const float*)&vC[bl][i];
        const float sc = Q0*ka[0] + Q1*ka[2] + Q2*kb[0] + Q3*kb[2];
        const float p  = ex2f(sc);
        sum += p;
        a0 += p * va[0]; a1 += p * va[2]; a2 += p * vc[0];
    }

    const float inv = rcpf(sum);

    // ============ epilogue for loop token (bl, t) ============
    const int dig = digs_sh[bl * T + t];
    const float2 tk = table_sh[dig];
    float x0 = tk.x + a0 * inv;       // x += out@Wq (pre-folded)
    float x1 = tk.y + a1 * inv;
    float x2 = __sinf((float)t * 1.0e-4f) + a2 * inv;

    // RMS ln2 + SwiGLU FFN
    float ms = (x0*x0 + x1*x1 + x2*x2) * (1.0f/3.0f) + 1e-6f;
    float r  = rsqrtf(ms);
    const float h0 = x0 * r * w_ln2[0];
    const float h1 = x1 * r * w_ln2[1];
    const float h2 = x2 * r * w_ln2[2];

    const float g0 = h0 * Wg[0] + h1 * Wg[1] + h2 * Wg[2];
    const float g1 = h0 * Wg[3] + h1 * Wg[4] + h2 * Wg[5];
    const float u0 = h0 * Wu[0] + h1 * Wu[1] + h2 * Wu[2];
    const float u1 = h0 * Wu[3] + h1 * Wu[4] + h2 * Wu[5];

    const float LOG2E = 1.4426950408889634f;
    const float m0 = g0 * u0 * rcpf(1.0f + ex2f(-g0 * LOG2E));  // silu(g0)*u0
    const float m1 = g1 * u1 * rcpf(1.0f + ex2f(-g1 * LOG2E));

    x0 += m0 * Wd[0] + m1 * Wd[1];
    x1 += m0 * Wd[2] + m1 * Wd[3];
    x2 += m0 * Wd[4] + m1 * Wd[5];

    // final RMS (only first two channels feed the logits)
    ms = (x0*x0 + x1*x1 + x2*x2) * (1.0f/3.0f) + 1e-6f;
    r  = rsqrtf(ms);
    const float f0 = x0 * r * w_lnf[0];
    const float f1 = x1 * r * w_lnf[1];

    // logits -> smem staging (per loop token)
    float* lg = &logits_sh[(bl * T + t) * VOCAB];
#pragma unroll
    for (int vv = 0; vv < VOCAB; ++vv) {
        const float2 tb = table_sh[vv];
        lg[vv] = f0 * tb.x + f1 * tb.y;
    }
    __syncthreads();

    // coalesced store: block owns a contiguous 2560-float span
    float2* dst2 = (float2*)(out + (size_t)blockIdx.x * (BPB * T * VOCAB));
    const float2* src2 = (const float2*)logits_sh;
#pragma unroll
    for (int i = tid; i < BPB * T * VOCAB / 2; i += NTHREADS)
        dst2[i] = src2[i];
}

extern "C" void kernel_launch(void* const* d_in, const int* in_sizes, int n_in,
                              void* d_out, int out_size)
{
    const int*   idx     = (const int*)  d_in[0];
    const float* arc_A   = (const float*)d_in[1];
    const float* arc_st  = (const float*)d_in[2];
    const float* arc_sd  = (const float*)d_in[3];
    const float* w_ln1   = (const float*)d_in[4];
    const float* w_ln2   = (const float*)d_in[5];
    const float* w_lnf   = (const float*)d_in[6];
    const float* w_qn    = (const float*)d_in[7];
    const float* Wq      = (const float*)d_in[8];
    const float* Wk      = (const float*)d_in[9];
    const float* Wg      = (const float*)d_in[10];
    const float* Wu      = (const float*)d_in[11];
    const float* Wd      = (const float*)d_in[12];
    float* out = (float*)d_out;

    const int B = in_sizes[0] / T;           // 16384
    const int grid = B / BPB;                // 4096 blocks
    adder_model_kernel<<<grid, NTHREADS>>>(idx, arc_A, arc_st, arc_sd,
                                           w_ln1, w_ln2, w_lnf, w_qn,
                                           Wq, Wk, Wg, Wu, Wd, out);
}

// round 14
// speedup vs baseline: 1.0247x; 1.0247x over previous
#include <cuda_runtime.h>

// R14: R12 base + dual-query lanes. Warp = 1 batch; lane l owns tokens
// t1=l and t2=l+32. Both active ranges are PREFIXES [0,np1), [0,np2) of the
// same pair-index sequence -> single lockstep loop, warp-uniform i, broadcast
// loads preserved, exit-only divergence. Each iteration's 4 loads feed two
// score chains -> loop L1 wavefronts per batch drop 192 -> 128 (-33%).
// q1 work predicated off for i>=np1 (prefix property). Everything else
// (packed fma.rn.f32x2, vq-folded Wq, intrinsic trig, smem-staged coalesced
// logits store) identical to R12.

#define T 64
#define WPB 8                      // warps = batches per block
#define NTHREADS (WPB * 32)
#define VOCAB 10

typedef unsigned long long u64;

__device__ __forceinline__ float ex2f(float x) {
    float y; asm("ex2.approx.ftz.f32 %0, %1;" : "=f"(y) : "f"(x)); return y;
}
__device__ __forceinline__ float rcpf(float x) {
    float y; asm("rcp.approx.ftz.f32 %0, %1;" : "=f"(y) : "f"(x)); return y;
}
__device__ __forceinline__ u64 pack2(float lo, float hi) {
    u64 r; asm("mov.b64 %0, {%1, %2};" : "=l"(r) : "f"(lo), "f"(hi)); return r;
}
__device__ __forceinline__ void unpack2(u64 v, float& lo, float& hi) {
    asm("mov.b64 {%0, %1}, %2;" : "=f"(lo), "=f"(hi) : "l"(v));
}
__device__ __forceinline__ u64 fma2(u64 a, u64 b, u64 c) {
    u64 d; asm("fma.rn.f32x2 %0, %1, %2, %3;" : "=l"(d) : "l"(a), "l"(b), "l"(c)); return d;
}
__device__ __forceinline__ u64 mul2(u64 a, u64 b) {
    u64 d; asm("mul.rn.f32x2 %0, %1, %2;" : "=l"(d) : "l"(a), "l"(b)); return d;
}
__device__ __forceinline__ u64 add2(u64 a, u64 b) {
    u64 d; asm("add.rn.f32x2 %0, %1, %2;" : "=l"(d) : "l"(a), "l"(b)); return d;
}

__global__ __launch_bounds__(NTHREADS)
void adder_model_kernel(
    const int* __restrict__ idx,
    const float* __restrict__ pA,
    const float* __restrict__ pStart,
    const float* __restrict__ pStride,
    const float* __restrict__ w_ln1,
    const float* __restrict__ w_ln2,
    const float* __restrict__ w_lnf,
    const float* __restrict__ w_qn,
    const float* __restrict__ Wq,
    const float* __restrict__ Wk,
    const float* __restrict__ Wg,
    const float* __restrict__ Wu,
    const float* __restrict__ Wd,
    float* __restrict__ out)
{
    __shared__ ulonglong2 kA[WPB][T / 2];
    __shared__ ulonglong2 kB[WPB][T / 2];
    __shared__ ulonglong2 vA[WPB][T / 2];   // (vq0 pair, vq1 pair)
    __shared__ u64        vC[WPB][T / 2];   // vq2 pair
    __shared__ float2 table_sh[VOCAB];
    __shared__ float  logits_sh[WPB * T * VOCAB];

    const int tid  = threadIdx.x;
    const int w    = tid >> 5;           // warp = batch within block
    const int lane = tid & 31;
    const int b    = blockIdx.x * WPB + w;

    const float A       = pA[0];
    const float astart  = pStart[0];
    const float astride = pStride[0];

    if (tid < VOCAB) {
        float s, c;
        __sincosf(astart + (float)tid * astride, &s, &c);
        table_sh[tid] = make_float2(A * c, A * s);
    }

    // ---- prologue: two tokens per lane (t = lane, lane+32) ----
    u64 Qd[2][4];
    int digs[2];

#pragma unroll
    for (int tk = 0; tk < 2; ++tk) {
        const int t = lane + 32 * tk;

        const int dig = idx[(size_t)b * T + t];
        digs[tk] = dig;
        float sa, ca;
        __sincosf(astart + (float)dig * astride, &sa, &ca);
        const float x0 = A * ca;
        const float x1 = A * sa;
        const float x2 = __sinf((float)t * 1.0e-4f);

        const float r = rsqrtf((x0*x0 + x1*x1 + x2*x2) * (1.0f/3.0f) + 1e-6f);
        const float h0 = x0 * r * w_ln1[0];
        const float h1 = x1 * r * w_ln1[1];
        const float h2 = x2 * r * w_ln1[2];

        float qr[4], kv[4];
#pragma unroll
        for (int j = 0; j < 4; ++j) {
            qr[j] = h0 * Wq[j*3+0] + h1 * Wq[j*3+1] + h2 * Wq[j*3+2];
            kv[j] = h0 * Wk[j*3+0] + h1 * Wk[j*3+1] + h2 * Wk[j*3+2];
        }

        const float vq0 = kv[0]*Wq[0] + kv[1]*Wq[3] + kv[2]*Wq[6] + kv[3]*Wq[9];
        const float vq1 = kv[0]*Wq[1] + kv[1]*Wq[4] + kv[2]*Wq[7] + kv[3]*Wq[10];
        const float vq2 = kv[0]*Wq[2] + kv[1]*Wq[5] + kv[2]*Wq[8] + kv[3]*Wq[11];

        const float wq0 = w_qn[0], wq1 = w_qn[1], wq2 = w_qn[2], wq3 = w_qn[3];
        const float rq = rsqrtf((qr[0]*qr[0]+qr[1]*qr[1]+qr[2]*qr[2]+qr[3]*qr[3]) * 0.25f + 1e-6f);
        const float rk = rsqrtf((kv[0]*kv[0]+kv[1]*kv[1]+kv[2]*kv[2]+kv[3]*kv[3]) * 0.25f + 1e-6f);
        const float q0 = qr[0]*rq*wq0, q1 = qr[1]*rq*wq1;
        const float q2 = qr[2]*rq*wq2, q3 = qr[3]*rq*wq3;
        const float k0 = kv[0]*rk*wq0, k1 = kv[1]*rk*wq1;
        const float k2 = kv[2]*rk*wq2, k3 = kv[3]*rk*wq3;

        float s0, c0, s1, c1;
        __sincosf((float)t, &s0, &c0);
        __sincosf((float)t * 0.57735026918962576f, &s1, &c1);

        const float SC = 0.5f * 1.4426950408889634f;
        const float Q0 = (q0*c0 - q1*s0) * SC, Q1 = (q0*s0 + q1*c0) * SC;
        const float Q2 = (q2*c1 - q3*s1) * SC, Q3 = (q2*s1 + q3*c1) * SC;
        const float K0 = k0*c0 - k1*s0, K1 = k0*s0 + k1*c0;
        const float K2 = k2*c1 - k3*s1, K3 = k2*s1 + k3*c1;

        Qd[tk][0] = pack2(Q0, Q0); Qd[tk][1] = pack2(Q1, Q1);
        Qd[tk][2] = pack2(Q2, Q2); Qd[tk][3] = pack2(Q3, Q3);

        const int i = t >> 1, par = t & 1;
        float* a = (float*)&kA[w][i]; a[par] = K0; a[2 + par] = K1;
        float* bb = (float*)&kB[w][i]; bb[par] = K2; bb[2 + par] = K3;
        float* c = (float*)&vA[w][i]; c[par] = vq0; c[2 + par] = vq1;
        float* d = (float*)&vC[w][i]; d[par] = vq2;
    }
    __syncthreads();

    // ---- dual-query lockstep loop ----
    const int np1 = (lane + 1) >> 1;        // prefix bound for t1 = lane
    const int np2 = (lane + 33) >> 1;       // prefix bound for t2 = lane+32

    u64 s1d = 0ULL, a1x = 0ULL, a1y = 0ULL, a1z = 0ULL;
    u64 s2d = 0ULL, a2x = 0ULL, a2y = 0ULL, a2z = 0ULL;

#pragma unroll 2
    for (int i = 0; i < np2; ++i) {
        const ulonglong2 ka = kA[w][i];
        const ulonglong2 kb = kB[w][i];
        const ulonglong2 va = vA[w][i];
        const u64 vc = vC[w][i];

        // q2 (always active)
        {
            const u64 sc = fma2(Qd[1][0], ka.x, fma2(Qd[1][1], ka.y,
                           fma2(Qd[1][2], kb.x, mul2(Qd[1][3], kb.y))));
            float sl, sh; unpack2(sc, sl, sh);
            const u64 p = pack2(ex2f(sl), ex2f(sh));
            s2d = add2(s2d, p);
            a2x = fma2(p, va.x, a2x);
            a2y = fma2(p, va.y, a2y);
            a2z = fma2(p, vc,   a2z);
        }
        // q1 (prefix-predicated)
        if (i < np1) {
            const u64 sc = fma2(Qd[0][0], ka.x, fma2(Qd[0][1], ka.y,
                           fma2(Qd[0][2], kb.x, mul2(Qd[0][3], kb.y))));
            float sl, sh; unpack2(sc, sl, sh);
            const u64 p = pack2(ex2f(sl), ex2f(sh));
            s1d = add2(s1d, p);
            a1x = fma2(p, va.x, a1x);
            a1y = fma2(p, va.y, a1y);
            a1z = fma2(p, vc,   a1z);
        }
    }

    float lo, hi;
    unpack2(s1d, lo, hi); float sum1 = lo + hi;
    unpack2(a1x, lo, hi); float o1x = lo + hi;
    unpack2(a1y, lo, hi); float o1y = lo + hi;
    unpack2(a1z, lo, hi); float o1z = lo + hi;
    unpack2(s2d, lo, hi); float sum2 = lo + hi;
    unpack2(a2x, lo, hi); float o2x = lo + hi;
    unpack2(a2y, lo, hi); float o2y = lo + hi;
    unpack2(a2z, lo, hi); float o2z = lo + hi;

    // ---- self terms (even lane -> both tokens even) ----
    if (!(lane & 1)) {
#pragma unroll
        for (int tk = 0; tk < 2; ++tk) {
            const int t = lane + 32 * tk;
            const int i = t >> 1;
            const float* ka = (const float*)&kA[w][i];
            const float* kb = (const float*)&kB[w][i];
            const float* va = (const float*)&vA[w][i];
            const float* vc = (const float*)&vC[w][i];
            float Q0, Q1, Q2, Q3, d0, d1;
            unpack2(Qd[tk][0], Q0, d0); unpack2(Qd[tk][1], Q1, d0);
            unpack2(Qd[tk][2], Q2, d1); unpack2(Qd[tk][3], Q3, d1);
            const float sc = Q0*ka[0] + Q1*ka[2] + Q2*kb[0] + Q3*kb[2];
            const float p  = ex2f(sc);
            if (tk == 0) {
                sum1 += p; o1x += p*va[0]; o1y += p*va[2]; o1z += p*vc[0];
            } else {
                sum2 += p; o2x += p*va[0]; o2y += p*va[2]; o2z += p*vc[0];
            }
        }
    }

    // ---- epilogue: two tokens per lane ----
#pragma unroll
    for (int tk = 0; tk < 2; ++tk) {
        const int t = lane + 32 * tk;
        const float inv = rcpf(tk ? sum2 : sum1);
        const float a0 = (tk ? o2x : o1x) * inv;
        const float a1 = (tk ? o2y : o1y) * inv;
        const float a2 = (tk ? o2z : o1z) * inv;

        const float2 tkv = table_sh[digs[tk]];
        float x0 = tkv.x + a0;               // x += out@Wq (pre-folded)
        float x1 = tkv.y + a1;
        float x2 = __sinf((float)t * 1.0e-4f) + a2;

        float ms = (x0*x0 + x1*x1 + x2*x2) * (1.0f/3.0f) + 1e-6f;
        float r  = rsqrtf(ms);
        const float h0 = x0 * r * w_ln2[0];
        const float h1 = x1 * r * w_ln2[1];
        const float h2 = x2 * r * w_ln2[2];

        const float g0 = h0 * Wg[0] + h1 * Wg[1] + h2 * Wg[2];
        const float g1 = h0 * Wg[3] + h1 * Wg[4] + h2 * Wg[5];
        const float u0 = h0 * Wu[0] + h1 * Wu[1] + h2 * Wu[2];
        const float u1 = h0 * Wu[3] + h1 * Wu[4] + h2 * Wu[5];

        const float LOG2E = 1.4426950408889634f;
        const float m0 = g0 * u0 * rcpf(1.0f + ex2f(-g0 * LOG2E));
        const float m1 = g1 * u1 * rcpf(1.0f + ex2f(-g1 * LOG2E));

        x0 += m0 * Wd[0] + m1 * Wd[1];
        x1 += m0 * Wd[2] + m1 * Wd[3];
        x2 += m0 * Wd[4] + m1 * Wd[5];

        ms = (x0*x0 + x1*x1 + x2*x2) * (1.0f/3.0f) + 1e-6f;
        r  = rsqrtf(ms);
        const float f0 = x0 * r * w_lnf[0];
        const float f1 = x1 * r * w_lnf[1];

        float* lg = &logits_sh[(w * T + t) * VOCAB];
#pragma unroll
        for (int vv = 0; vv < VOCAB; ++vv) {
            const float2 tb = table_sh[vv];
            lg[vv] = f0 * tb.x + f1 * tb.y;
        }
    }
    __syncthreads();

    // ---- coalesced store: block owns a contiguous 5120-float span ----
    float2* dst2 = (float2*)(out + (size_t)blockIdx.x * (WPB * T * VOCAB));
    const float2* src2 = (const float2*)logits_sh;
#pragma unroll
    for (int i = tid; i < WPB * T * VOCAB / 2; i += NTHREADS)
        dst2[i] = src2[i];
}

extern "C" void kernel_launch(void* const* d_in, const int* in_sizes, int n_in,
                              void* d_out, int out_size)
{
    const int*   idx     = (const int*)  d_in[0];
    const float* arc_A   = (const float*)d_in[1];
    const float* arc_st  = (const float*)d_in[2];
    const float* arc_sd  = (const float*)d_in[3];
    const float* w_ln1   = (const float*)d_in[4];
    const float* w_ln2   = (const float*)d_in[5];
    const float* w_lnf   = (const float*)d_in[6];
    const float* w_qn    = (const float*)d_in[7];
    const float* Wq      = (const float*)d_in[8];
    const float* Wk      = (const float*)d_in[9];
    const float* Wg      = (const float*)d_in[10];
    const float* Wu      = (const float*)d_in[11];
    const float* Wd      = (const float*)d_in[12];
    float* out = (float*)d_out;

    const int B = in_sizes[0] / T;           // 16384
    const int grid = B / WPB;                // 2048 blocks
    adder_model_kernel<<<grid, NTHREADS>>>(idx, arc_A, arc_st, arc_sd,
                                           w_ln1, w_ln2, w_lnf, w_qn,
                                           Wq, Wk, Wg, Wu, Wd, out);
}

// round 15
// speedup vs baseline: 1.0771x; 1.0511x over previous
#include <cuda_runtime.h>

// R15: R14 (dual-query lanes, 41.4us) + hoisted (dig,t) tables.
// All prologue trig/projection/RMS work depends only on (dig,t) -> 640
// entries. A tiny precompute kernel builds AoS tables (Q pre-scaled by
// 0.5*log2e, V pre-projected through Wq); the main prologue collapses to
// 1 idx load + 3 float4 gathers (L1/L2-hot) + smem staging.
// Loop + epilogue + coalesced store identical to R14.

#define T 64
#define WPB 8                      // warps = batches per block
#define NTHREADS (WPB * 32)
#define VOCAB 10

typedef unsigned long long u64;

__device__ float4 g_q4[VOCAB * T];   // scaled RoPE'd Q
__device__ float4 g_k4[VOCAB * T];   // RoPE'd K
__device__ float4 g_v4[VOCAB * T];   // (vq0, vq1, vq2, unused) = v @ Wq

__device__ __forceinline__ float ex2f(float x) {
    float y; asm("ex2.approx.ftz.f32 %0, %1;" : "=f"(y) : "f"(x)); return y;
}
__device__ __forceinline__ float rcpf(float x) {
    float y; asm("rcp.approx.ftz.f32 %0, %1;" : "=f"(y) : "f"(x)); return y;
}
__device__ __forceinline__ u64 pack2(float lo, float hi) {
    u64 r; asm("mov.b64 %0, {%1, %2};" : "=l"(r) : "f"(lo), "f"(hi)); return r;
}
__device__ __forceinline__ void unpack2(u64 v, float& lo, float& hi) {
    asm("mov.b64 {%0, %1}, %2;" : "=f"(lo), "=f"(hi) : "l"(v));
}
__device__ __forceinline__ u64 fma2(u64 a, u64 b, u64 c) {
    u64 d; asm("fma.rn.f32x2 %0, %1, %2, %3;" : "=l"(d) : "l"(a), "l"(b), "l"(c)); return d;
}
__device__ __forceinline__ u64 mul2(u64 a, u64 b) {
    u64 d; asm("mul.rn.f32x2 %0, %1, %2;" : "=l"(d) : "l"(a), "l"(b)); return d;
}
__device__ __forceinline__ u64 add2(u64 a, u64 b) {
    u64 d; asm("add.rn.f32x2 %0, %1, %2;" : "=l"(d) : "l"(a), "l"(b)); return d;
}

// ---------------- kernel 1: 640-entry AoS tables ----------------
__global__ void precompute_kernel(
    const float* __restrict__ pA,
    const float* __restrict__ pS,
    const float* __restrict__ pD,
    const float* __restrict__ w_ln1,
    const float* __restrict__ w_qn,
    const float* __restrict__ Wq,
    const float* __restrict__ Wk)
{
    const int dig = blockIdx.x;    // 0..9
    const int t   = threadIdx.x;   // 0..63

    const float A = pA[0], ast = pS[0], astr = pD[0];
    float sa, ca;
    __sincosf(ast + (float)dig * astr, &sa, &ca);
    const float x0 = A * ca;
    const float x1 = A * sa;
    const float x2 = __sinf((float)t * 1.0e-4f);

    const float r = rsqrtf((x0*x0 + x1*x1 + x2*x2) * (1.0f/3.0f) + 1e-6f);
    const float h0 = x0 * r * w_ln1[0];
    const float h1 = x1 * r * w_ln1[1];
    const float h2 = x2 * r * w_ln1[2];

    float qr[4], kv[4];
#pragma unroll
    for (int j = 0; j < 4; ++j) {
        qr[j] = h0 * Wq[j*3+0] + h1 * Wq[j*3+1] + h2 * Wq[j*3+2];
        kv[j] = h0 * Wk[j*3+0] + h1 * Wk[j*3+1] + h2 * Wk[j*3+2];
    }

    const float vq0 = kv[0]*Wq[0] + kv[1]*Wq[3] + kv[2]*Wq[6] + kv[3]*Wq[9];
    const float vq1 = kv[0]*Wq[1] + kv[1]*Wq[4] + kv[2]*Wq[7] + kv[3]*Wq[10];
    const float vq2 = kv[0]*Wq[2] + kv[1]*Wq[5] + kv[2]*Wq[8] + kv[3]*Wq[11];

    const float rq = rsqrtf((qr[0]*qr[0]+qr[1]*qr[1]+qr[2]*qr[2]+qr[3]*qr[3]) * 0.25f + 1e-6f);
    const float rk = rsqrtf((kv[0]*kv[0]+kv[1]*kv[1]+kv[2]*kv[2]+kv[3]*kv[3]) * 0.25f + 1e-6f);
    const float q0 = qr[0]*rq*w_qn[0], q1 = qr[1]*rq*w_qn[1];
    const float q2 = qr[2]*rq*w_qn[2], q3 = qr[3]*rq*w_qn[3];
    const float k0 = kv[0]*rk*w_qn[0], k1 = kv[1]*rk*w_qn[1];
    const float k2 = kv[2]*rk*w_qn[2], k3 = kv[3]*rk*w_qn[3];

    float s0, c0, s1, c1;
    __sincosf((float)t, &s0, &c0);
    __sincosf((float)t * 0.57735026918962576f, &s1, &c1);

    const float SC = 0.5f * 1.4426950408889634f;   // scale * log2(e)
    const int e = dig * T + t;
    g_q4[e] = make_float4((q0*c0 - q1*s0)*SC, (q0*s0 + q1*c0)*SC,
                          (q2*c1 - q3*s1)*SC, (q2*s1 + q3*c1)*SC);
    g_k4[e] = make_float4(k0*c0 - k1*s0, k0*s0 + k1*c0,
                          k2*c1 - k3*s1, k2*s1 + k3*c1);
    g_v4[e] = make_float4(vq0, vq1, vq2, 0.0f);
}

// ---------------- kernel 2: attention + FFN + logits ----------------
__global__ __launch_bounds__(NTHREADS)
void adder_model_kernel(
    const int* __restrict__ idx,
    const float* __restrict__ pA,
    const float* __restrict__ pStart,
    const float* __restrict__ pStride,
    const float* __restrict__ w_ln2,
    const float* __restrict__ w_lnf,
    const float* __restrict__ Wg,
    const float* __restrict__ Wu,
    const float* __restrict__ Wd,
    float* __restrict__ out)
{
    __shared__ ulonglong2 kA[WPB][T / 2];
    __shared__ ulonglong2 kB[WPB][T / 2];
    __shared__ ulonglong2 vA[WPB][T / 2];   // (vq0 pair, vq1 pair)
    __shared__ u64        vC[WPB][T / 2];   // vq2 pair
    __shared__ float2 table_sh[VOCAB];
    __shared__ float  logits_sh[WPB * T * VOCAB];

    const int tid  = threadIdx.x;
    const int w    = tid >> 5;           // warp = batch within block
    const int lane = tid & 31;
    const int b    = blockIdx.x * WPB + w;

    if (tid < VOCAB) {
        float s, c;
        __sincosf(pStart[0] + (float)tid * pStride[0], &s, &c);
        const float A = pA[0];
        table_sh[tid] = make_float2(A * c, A * s);
    }

    // ---- prologue: two tokens per lane, 3 gathers each ----
    u64 Qd[2][4];
    int digs[2];

#pragma unroll
    for (int tk = 0; tk < 2; ++tk) {
        const int t = lane + 32 * tk;
        const int dig = idx[(size_t)b * T + t];
        digs[tk] = dig;
        const int e = dig * T + t;

        const float4 q = g_q4[e];
        const float4 k = g_k4[e];
        const float4 v = g_v4[e];

        Qd[tk][0] = pack2(q.x, q.x); Qd[tk][1] = pack2(q.y, q.y);
        Qd[tk][2] = pack2(q.z, q.z); Qd[tk][3] = pack2(q.w, q.w);

        const int i = t >> 1, par = t & 1;
        float* a = (float*)&kA[w][i]; a[par] = k.x; a[2 + par] = k.y;
        float* bb = (float*)&kB[w][i]; bb[par] = k.z; bb[2 + par] = k.w;
        float* c = (float*)&vA[w][i]; c[par] = v.x; c[2 + par] = v.y;
        float* d = (float*)&vC[w][i]; d[par] = v.z;
    }
    __syncthreads();

    // ---- dual-query lockstep loop (identical to R14) ----
    const int np1 = (lane + 1) >> 1;        // prefix bound for t1 = lane
    const int np2 = (lane + 33) >> 1;       // prefix bound for t2 = lane+32

    u64 s1d = 0ULL, a1x = 0ULL, a1y = 0ULL, a1z = 0ULL;
    u64 s2d = 0ULL, a2x = 0ULL, a2y = 0ULL, a2z = 0ULL;

#pragma unroll 2
    for (int i = 0; i < np2; ++i) {
        const ulonglong2 ka = kA[w][i];
        const ulonglong2 kb = kB[w][i];
        const ulonglong2 va = vA[w][i];
        const u64 vc = vC[w][i];

        // q2 (always active)
        {
            const u64 sc = fma2(Qd[1][0], ka.x, fma2(Qd[1][1], ka.y,
                           fma2(Qd[1][2], kb.x, mul2(Qd[1][3], kb.y))));
            float sl, sh; unpack2(sc, sl, sh);
            const u64 p = pack2(ex2f(sl), ex2f(sh));
            s2d = add2(s2d, p);
            a2x = fma2(p, va.x, a2x);
            a2y = fma2(p, va.y, a2y);
            a2z = fma2(p, vc,   a2z);
        }
        // q1 (prefix-predicated)
        if (i < np1) {
            const u64 sc = fma2(Qd[0][0], ka.x, fma2(Qd[0][1], ka.y,
                           fma2(Qd[0][2], kb.x, mul2(Qd[0][3], kb.y))));
            float sl, sh; unpack2(sc, sl, sh);
            const u64 p = pack2(ex2f(sl), ex2f(sh));
            s1d = add2(s1d, p);
            a1x = fma2(p, va.x, a1x);
            a1y = fma2(p, va.y, a1y);
            a1z = fma2(p, vc,   a1z);
        }
    }

    float lo, hi;
    unpack2(s1d, lo, hi); float sum1 = lo + hi;
    unpack2(a1x, lo, hi); float o1x = lo + hi;
    unpack2(a1y, lo, hi); float o1y = lo + hi;
    unpack2(a1z, lo, hi); float o1z = lo + hi;
    unpack2(s2d, lo, hi); float sum2 = lo + hi;
    unpack2(a2x, lo, hi); float o2x = lo + hi;
    unpack2(a2y, lo, hi); float o2y = lo + hi;
    unpack2(a2z, lo, hi); float o2z = lo + hi;

    // ---- self terms (even lane -> both tokens even) ----
    if (!(lane & 1)) {
#pragma unroll
        for (int tk = 0; tk < 2; ++tk) {
            const int t = lane + 32 * tk;
            const int i = t >> 1;
            const float* ka = (const float*)&kA[w][i];
            const float* kb = (const float*)&kB[w][i];
            const float* va = (const float*)&vA[w][i];
            const float* vc = (const float*)&vC[w][i];
            float Q0, Q1, Q2, Q3, d0, d1;
            unpack2(Qd[tk][0], Q0, d0); unpack2(Qd[tk][1], Q1, d0);
            unpack2(Qd[tk][2], Q2, d1); unpack2(Qd[tk][3], Q3, d1);
            const float sc = Q0*ka[0] + Q1*ka[2] + Q2*kb[0] + Q3*kb[2];
            const float p  = ex2f(sc);
            if (tk == 0) {
                sum1 += p; o1x += p*va[0]; o1y += p*va[2]; o1z += p*vc[0];
            } else {
                sum2 += p; o2x += p*va[0]; o2y += p*va[2]; o2z += p*vc[0];
            }
        }
    }

    // ---- epilogue: two tokens per lane ----
#pragma unroll
    for (int tk = 0; tk < 2; ++tk) {
        const int t = lane + 32 * tk;
        const float inv = rcpf(tk ? sum2 : sum1);
        const float a0 = (tk ? o2x : o1x) * inv;
        const float a1 = (tk ? o2y : o1y) * inv;
        const float a2 = (tk ? o2z : o1z) * inv;

        const float2 tkv = table_sh[digs[tk]];
        float x0 = tkv.x + a0;               // x += out@Wq (pre-folded)
        float x1 = tkv.y + a1;
        float x2 = __sinf((float)t * 1.0e-4f) + a2;

        float ms = (x0*x0 + x1*x1 + x2*x2) * (1.0f/3.0f) + 1e-6f;
        float r  = rsqrtf(ms);
        const float h0 = x0 * r * w_ln2[0];
        const float h1 = x1 * r * w_ln2[1];
        const float h2 = x2 * r * w_ln2[2];

        const float g0 = h0 * Wg[0] + h1 * Wg[1] + h2 * Wg[2];
        const float g1 = h0 * Wg[3] + h1 * Wg[4] + h2 * Wg[5];
        const float u0 = h0 * Wu[0] + h1 * Wu[1] + h2 * Wu[2];
        const float u1 = h0 * Wu[3] + h1 * Wu[4] + h2 * Wu[5];

        const float LOG2E = 1.4426950408889634f;
        const float m0 = g0 * u0 * rcpf(1.0f + ex2f(-g0 * LOG2E));
        const float m1 = g1 * u1 * rcpf(1.0f + ex2f(-g1 * LOG2E));

        x0 += m0 * Wd[0] + m1 * Wd[1];
        x1 += m0 * Wd[2] + m1 * Wd[3];
        x2 += m0 * Wd[4] + m1 * Wd[5];

        ms = (x0*x0 + x1*x1 + x2*x2) * (1.0f/3.0f) + 1e-6f;
        r  = rsqrtf(ms);
        const float f0 = x0 * r * w_lnf[0];
        const float f1 = x1 * r * w_lnf[1];

        float* lg = &logits_sh[(w * T + t) * VOCAB];
#pragma unroll
        for (int vv = 0; vv < VOCAB; ++vv) {
            const float2 tb = table_sh[vv];
            lg[vv] = f0 * tb.x + f1 * tb.y;
        }
    }
    __syncthreads();

    // ---- coalesced store: block owns a contiguous 5120-float span ----
    float2* dst2 = (float2*)(out + (size_t)blockIdx.x * (WPB * T * VOCAB));
    const float2* src2 = (const float2*)logits_sh;
#pragma unroll
    for (int i = tid; i < WPB * T * VOCAB / 2; i += NTHREADS)
        dst2[i] = src2[i];
}

extern "C" void kernel_launch(void* const* d_in, const int* in_sizes, int n_in,
                              void* d_out, int out_size)
{
    const int*   idx     = (const int*)  d_in[0];
    const float* arc_A   = (const float*)d_in[1];
    const float* arc_st  = (const float*)d_in[2];
    const float* arc_sd  = (const float*)d_in[3];
    const float* w_ln1   = (const float*)d_in[4];
    const float* w_ln2   = (const float*)d_in[5];
    const float* w_lnf   = (const float*)d_in[6];
    const float* w_qn    = (const float*)d_in[7];
    const float* Wq      = (const float*)d_in[8];
    const float* Wk      = (const float*)d_in[9];
    const float* Wg      = (const float*)d_in[10];
    const float* Wu      = (const float*)d_in[11];
    const float* Wd      = (const float*)d_in[12];
    float* out = (float*)d_out;

    precompute_kernel<<<VOCAB, T>>>(arc_A, arc_st, arc_sd, w_ln1, w_qn, Wq, Wk);

    const int B = in_sizes[0] / T;           // 16384
    const int grid = B / WPB;                // 2048 blocks
    adder_model_kernel<<<grid, NTHREADS>>>(idx, arc_A, arc_st, arc_sd,
                                           w_ln2, w_lnf, Wg, Wu, Wd, out);
}

// round 16
// speedup vs baseline: 1.1361x; 1.0548x over previous
#include <cuda_runtime.h>

// R16: R15 (39.4us best: table-hoisted prologue + dual-query lanes) with
// __launch_bounds__(256, 4): forces regs <=64 -> 4 CTAs/SM (occ 35%->~47%).
// The kernel is latency-limited (issue 55%, no pipe saturated); more warps
// in flight is the cheapest lever. Everything else identical to R15.

#define T 64
#define WPB 8                      // warps = batches per block
#define NTHREADS (WPB * 32)
#define VOCAB 10

typedef unsigned long long u64;

__device__ float4 g_q4[VOCAB * T];   // scaled RoPE'd Q
__device__ float4 g_k4[VOCAB * T];   // RoPE'd K
__device__ float4 g_v4[VOCAB * T];   // (vq0, vq1, vq2, unused) = v @ Wq

__device__ __forceinline__ float ex2f(float x) {
    float y; asm("ex2.approx.ftz.f32 %0, %1;" : "=f"(y) : "f"(x)); return y;
}
__device__ __forceinline__ float rcpf(float x) {
    float y; asm("rcp.approx.ftz.f32 %0, %1;" : "=f"(y) : "f"(x)); return y;
}
__device__ __forceinline__ u64 pack2(float lo, float hi) {
    u64 r; asm("mov.b64 %0, {%1, %2};" : "=l"(r) : "f"(lo), "f"(hi)); return r;
}
__device__ __forceinline__ void unpack2(u64 v, float& lo, float& hi) {
    asm("mov.b64 {%0, %1}, %2;" : "=f"(lo), "=f"(hi) : "l"(v));
}
__device__ __forceinline__ u64 fma2(u64 a, u64 b, u64 c) {
    u64 d; asm("fma.rn.f32x2 %0, %1, %2, %3;" : "=l"(d) : "l"(a), "l"(b), "l"(c)); return d;
}
__device__ __forceinline__ u64 mul2(u64 a, u64 b) {
    u64 d; asm("mul.rn.f32x2 %0, %1, %2;" : "=l"(d) : "l"(a), "l"(b)); return d;
}
__device__ __forceinline__ u64 add2(u64 a, u64 b) {
    u64 d; asm("add.rn.f32x2 %0, %1, %2;" : "=l"(d) : "l"(a), "l"(b)); return d;
}

// ---------------- kernel 1: 640-entry AoS tables ----------------
__global__ void precompute_kernel(
    const float* __restrict__ pA,
    const float* __restrict__ pS,
    const float* __restrict__ pD,
    const float* __restrict__ w_ln1,
    const float* __restrict__ w_qn,
    const float* __restrict__ Wq,
    const float* __restrict__ Wk)
{
    const int dig = blockIdx.x;    // 0..9
    const int t   = threadIdx.x;   // 0..63

    const float A = pA[0], ast = pS[0], astr = pD[0];
    float sa, ca;
    __sincosf(ast + (float)dig * astr, &sa, &ca);
    const float x0 = A * ca;
    const float x1 = A * sa;
    const float x2 = __sinf((float)t * 1.0e-4f);

    const float r = rsqrtf((x0*x0 + x1*x1 + x2*x2) * (1.0f/3.0f) + 1e-6f);
    const float h0 = x0 * r * w_ln1[0];
    const float h1 = x1 * r * w_ln1[1];
    const float h2 = x2 * r * w_ln1[2];

    float qr[4], kv[4];
#pragma unroll
    for (int j = 0; j < 4; ++j) {
        qr[j] = h0 * Wq[j*3+0] + h1 * Wq[j*3+1] + h2 * Wq[j*3+2];
        kv[j] = h0 * Wk[j*3+0] + h1 * Wk[j*3+1] + h2 * Wk[j*3+2];
    }

    const float vq0 = kv[0]*Wq[0] + kv[1]*Wq[3] + kv[2]*Wq[6] + kv[3]*Wq[9];
    const float vq1 = kv[0]*Wq[1] + kv[1]*Wq[4] + kv[2]*Wq[7] + kv[3]*Wq[10];
    const float vq2 = kv[0]*Wq[2] + kv[1]*Wq[5] + kv[2]*Wq[8] + kv[3]*Wq[11];

    const float rq = rsqrtf((qr[0]*qr[0]+qr[1]*qr[1]+qr[2]*qr[2]+qr[3]*qr[3]) * 0.25f + 1e-6f);
    const float rk = rsqrtf((kv[0]*kv[0]+kv[1]*kv[1]+kv[2]*kv[2]+kv[3]*kv[3]) * 0.25f + 1e-6f);
    const float q0 = qr[0]*rq*w_qn[0], q1 = qr[1]*rq*w_qn[1];
    const float q2 = qr[2]*rq*w_qn[2], q3 = qr[3]*rq*w_qn[3];
    const float k0 = kv[0]*rk*w_qn[0], k1 = kv[1]*rk*w_qn[1];
    const float k2 = kv[2]*rk*w_qn[2], k3 = kv[3]*rk*w_qn[3];

    float s0, c0, s1, c1;
    __sincosf((float)t, &s0, &c0);
    __sincosf((float)t * 0.57735026918962576f, &s1, &c1);

    const float SC = 0.5f * 1.4426950408889634f;   // scale * log2(e)
    const int e = dig * T + t;
    g_q4[e] = make_float4((q0*c0 - q1*s0)*SC, (q0*s0 + q1*c0)*SC,
                          (q2*c1 - q3*s1)*SC, (q2*s1 + q3*c1)*SC);
    g_k4[e] = make_float4(k0*c0 - k1*s0, k0*s0 + k1*c0,
                          k2*c1 - k3*s1, k2*s1 + k3*c1);
    g_v4[e] = make_float4(vq0, vq1, vq2, 0.0f);
}

// ---------------- kernel 2: attention + FFN + logits ----------------
__global__ __launch_bounds__(NTHREADS, 4)
void adder_model_kernel(
    const int* __restrict__ idx,
    const float* __restrict__ pA,
    const float* __restrict__ pStart,
    const float* __restrict__ pStride,
    const float* __restrict__ w_ln2,
    const float* __restrict__ w_lnf,
    const float* __restrict__ Wg,
    const float* __restrict__ Wu,
    const float* __restrict__ Wd,
    float* __restrict__ out)
{
    __shared__ ulonglong2 kA[WPB][T / 2];
    __shared__ ulonglong2 kB[WPB][T / 2];
    __shared__ ulonglong2 vA[WPB][T / 2];   // (vq0 pair, vq1 pair)
    __shared__ u64        vC[WPB][T / 2];   // vq2 pair
    __shared__ float2 table_sh[VOCAB];
    __shared__ float  logits_sh[WPB * T * VOCAB];

    const int tid  = threadIdx.x;
    const int w    = tid >> 5;           // warp = batch within block
    const int lane = tid & 31;
    const int b    = blockIdx.x * WPB + w;

    if (tid < VOCAB) {
        float s, c;
        __sincosf(pStart[0] + (float)tid * pStride[0], &s, &c);
        const float A = pA[0];
        table_sh[tid] = make_float2(A * c, A * s);
    }

    // ---- prologue: two tokens per lane, 3 gathers each ----
    u64 Qd[2][4];
    int digs[2];

#pragma unroll
    for (int tk = 0; tk < 2; ++tk) {
        const int t = lane + 32 * tk;
        const int dig = idx[(size_t)b * T + t];
        digs[tk] = dig;
        const int e = dig * T + t;

        const float4 q = g_q4[e];
        const float4 k = g_k4[e];
        const float4 v = g_v4[e];

        Qd[tk][0] = pack2(q.x, q.x); Qd[tk][1] = pack2(q.y, q.y);
        Qd[tk][2] = pack2(q.z, q.z); Qd[tk][3] = pack2(q.w, q.w);

        const int i = t >> 1, par = t & 1;
        float* a = (float*)&kA[w][i]; a[par] = k.x; a[2 + par] = k.y;
        float* bb = (float*)&kB[w][i]; bb[par] = k.z; bb[2 + par] = k.w;
        float* c = (float*)&vA[w][i]; c[par] = v.x; c[2 + par] = v.y;
        float* d = (float*)&vC[w][i]; d[par] = v.z;
    }
    __syncthreads();

    // ---- dual-query lockstep loop ----
    const int np1 = (lane + 1) >> 1;        // prefix bound for t1 = lane
    const int np2 = (lane + 33) >> 1;       // prefix bound for t2 = lane+32

    u64 s1d = 0ULL, a1x = 0ULL, a1y = 0ULL, a1z = 0ULL;
    u64 s2d = 0ULL, a2x = 0ULL, a2y = 0ULL, a2z = 0ULL;

#pragma unroll 2
    for (int i = 0; i < np2; ++i) {
        const ulonglong2 ka = kA[w][i];
        const ulonglong2 kb = kB[w][i];
        const ulonglong2 va = vA[w][i];
        const u64 vc = vC[w][i];

        // q2 (always active)
        {
            const u64 sc = fma2(Qd[1][0], ka.x, fma2(Qd[1][1], ka.y,
                           fma2(Qd[1][2], kb.x, mul2(Qd[1][3], kb.y))));
            float sl, sh; unpack2(sc, sl, sh);
            const u64 p = pack2(ex2f(sl), ex2f(sh));
            s2d = add2(s2d, p);
            a2x = fma2(p, va.x, a2x);
            a2y = fma2(p, va.y, a2y);
            a2z = fma2(p, vc,   a2z);
        }
        // q1 (prefix-predicated)
        if (i < np1) {
            const u64 sc = fma2(Qd[0][0], ka.x, fma2(Qd[0][1], ka.y,
                           fma2(Qd[0][2], kb.x, mul2(Qd[0][3], kb.y))));
            float sl, sh; unpack2(sc, sl, sh);
            const u64 p = pack2(ex2f(sl), ex2f(sh));
            s1d = add2(s1d, p);
            a1x = fma2(p, va.x, a1x);
            a1y = fma2(p, va.y, a1y);
            a1z = fma2(p, vc,   a1z);
        }
    }

    float lo, hi;
    unpack2(s1d, lo, hi); float sum1 = lo + hi;
    unpack2(a1x, lo, hi); float o1x = lo + hi;
    unpack2(a1y, lo, hi); float o1y = lo + hi;
    unpack2(a1z, lo, hi); float o1z = lo + hi;
    unpack2(s2d, lo, hi); float sum2 = lo + hi;
    unpack2(a2x, lo, hi); float o2x = lo + hi;
    unpack2(a2y, lo, hi); float o2y = lo + hi;
    unpack2(a2z, lo, hi); float o2z = lo + hi;

    // ---- self terms (even lane -> both tokens even) ----
    if (!(lane & 1)) {
#pragma unroll
        for (int tk = 0; tk < 2; ++tk) {
            const int t = lane + 32 * tk;
            const int i = t >> 1;
            const float* ka = (const float*)&kA[w][i];
            const float* kb = (const float*)&kB[w][i];
            const float* va = (const float*)&vA[w][i];
            const float* vc = (const float*)&vC[w][i];
            float Q0, Q1, Q2, Q3, d0, d1;
            unpack2(Qd[tk][0], Q0, d0); unpack2(Qd[tk][1], Q1, d0);
            unpack2(Qd[tk][2], Q2, d1); unpack2(Qd[tk][3], Q3, d1);
            const float sc = Q0*ka[0] + Q1*ka[2] + Q2*kb[0] + Q3*kb[2];
            const float p  = ex2f(sc);
            if (tk == 0) {
                sum1 += p; o1x += p*va[0]; o1y += p*va[2]; o1z += p*vc[0];
            } else {
                sum2 += p; o2x += p*va[0]; o2y += p*va[2]; o2z += p*vc[0];
            }
        }
    }

    // ---- epilogue: two tokens per lane ----
#pragma unroll
    for (int tk = 0; tk < 2; ++tk) {
        const int t = lane + 32 * tk;
        const float inv = rcpf(tk ? sum2 : sum1);
        const float a0 = (tk ? o2x : o1x) * inv;
        const float a1 = (tk ? o2y : o1y) * inv;
        const float a2 = (tk ? o2z : o1z) * inv;

        const float2 tkv = table_sh[digs[tk]];
        float x0 = tkv.x + a0;               // x += out@Wq (pre-folded)
        float x1 = tkv.y + a1;
        float x2 = __sinf((float)t * 1.0e-4f) + a2;

        float ms = (x0*x0 + x1*x1 + x2*x2) * (1.0f/3.0f) + 1e-6f;
        float r  = rsqrtf(ms);
        const float h0 = x0 * r * w_ln2[0];
        const float h1 = x1 * r * w_ln2[1];
        const float h2 = x2 * r * w_ln2[2];

        const float g0 = h0 * Wg[0] + h1 * Wg[1] + h2 * Wg[2];
        const float g1 = h0 * Wg[3] + h1 * Wg[4] + h2 * Wg[5];
        const float u0 = h0 * Wu[0] + h1 * Wu[1] + h2 * Wu[2];
        const float u1 = h0 * Wu[3] + h1 * Wu[4] + h2 * Wu[5];

        const float LOG2E = 1.4426950408889634f;
        const float m0 = g0 * u0 * rcpf(1.0f + ex2f(-g0 * LOG2E));
        const float m1 = g1 * u1 * rcpf(1.0f + ex2f(-g1 * LOG2E));

        x0 += m0 * Wd[0] + m1 * Wd[1];
        x1 += m0 * Wd[2] + m1 * Wd[3];
        x2 += m0 * Wd[4] + m1 * Wd[5];

        ms = (x0*x0 + x1*x1 + x2*x2) * (1.0f/3.0f) + 1e-6f;
        r  = rsqrtf(ms);
        const float f0 = x0 * r * w_lnf[0];
        const float f1 = x1 * r * w_lnf[1];

        float* lg = &logits_sh[(w * T + t) * VOCAB];
#pragma unroll
        for (int vv = 0; vv < VOCAB; ++vv) {
            const float2 tb = table_sh[vv];
            lg[vv] = f0 * tb.x + f1 * tb.y;
        }
    }
    __syncthreads();

    // ---- coalesced store: block owns a contiguous 5120-float span ----
    float2* dst2 = (float2*)(out + (size_t)blockIdx.x * (WPB * T * VOCAB));
    const float2* src2 = (const float2*)logits_sh;
#pragma unroll
    for (int i = tid; i < WPB * T * VOCAB / 2; i += NTHREADS)
        dst2[i] = src2[i];
}

extern "C" void kernel_launch(void* const* d_in, const int* in_sizes, int n_in,
                              void* d_out, int out_size)
{
    const int*   idx     = (const int*)  d_in[0];
    const float* arc_A   = (const float*)d_in[1];
    const float* arc_st  = (const float*)d_in[2];
    const float* arc_sd  = (const float*)d_in[3];
    const float* w_ln1   = (const float*)d_in[4];
    const float* w_ln2   = (const float*)d_in[5];
    const float* w_lnf   = (const float*)d_in[6];
    const float* w_qn    = (const float*)d_in[7];
    const float* Wq      = (const float*)d_in[8];
    const float* Wk      = (const float*)d_in[9];
    const float* Wg      = (const float*)d_in[10];
    const float* Wu      = (const float*)d_in[11];
    const float* Wd      = (const float*)d_in[12];
    float* out = (float*)d_out;

    precompute_kernel<<<VOCAB, T>>>(arc_A, arc_st, arc_sd, w_ln1, w_qn, Wq, Wk);

    const int B = in_sizes[0] / T;           // 16384
    const int grid = B / WPB;                // 2048 blocks
    adder_model_kernel<<<grid, NTHREADS>>>(idx, arc_A, arc_st, arc_sd,
                                           w_ln2, w_lnf, Wg, Wu, Wd, out);
}